// round 1
// baseline (speedup 1.0000x reference)
#include <cuda_runtime.h>
#include <math.h>

#define N_NODES 100000
#define N_EDGES 3200000
#define N_GRAPHS 512
#define D_FEAT 128
#define D_HID 32

// Scratch buffers (allocation-free rule: __device__ globals)
__device__ __align__(16) float d_A[N_NODES * D_HID];   // projected features (gather source)
__device__ __align__(16) float d_S[N_NODES * D_HID];   // spmm accumulator (scatter dest)
__device__ float d_pool[N_GRAPHS * D_HID];

__device__ __forceinline__ float elu_f(float x) { return x > 0.f ? x : expm1f(x); }

// ---------------------------------------------------------------------------
// Layer 1 projection: d_A = x @ W1   (x: [N,128], W1: [128,32])
// Thread per node; W1 staged in smem (warp-uniform broadcast loads).
// ---------------------------------------------------------------------------
__global__ void __launch_bounds__(128) proj1_kernel(const float* __restrict__ x,
                                                    const float* __restrict__ W) {
    __shared__ float sW[D_FEAT * D_HID];
    for (int i = threadIdx.x; i < D_FEAT * D_HID; i += 128) sW[i] = W[i];
    __syncthreads();

    int n = blockIdx.x * 128 + threadIdx.x;
    if (n >= N_NODES) return;

    float acc[D_HID];
#pragma unroll
    for (int j = 0; j < D_HID; j++) acc[j] = 0.f;

    const float4* xr = reinterpret_cast<const float4*>(x) + (size_t)n * (D_FEAT / 4);
#pragma unroll 4
    for (int k4 = 0; k4 < D_FEAT / 4; k4++) {
        float4 v = xr[k4];
        const float* w0 = &sW[(k4 * 4 + 0) * D_HID];
        const float* w1 = &sW[(k4 * 4 + 1) * D_HID];
        const float* w2 = &sW[(k4 * 4 + 2) * D_HID];
        const float* w3 = &sW[(k4 * 4 + 3) * D_HID];
#pragma unroll
        for (int j = 0; j < D_HID; j++)
            acc[j] += v.x * w0[j] + v.y * w1[j] + v.z * w2[j] + v.w * w3[j];
    }

    float4* out4 = reinterpret_cast<float4*>(d_A) + (size_t)n * (D_HID / 4);
#pragma unroll
    for (int q = 0; q < D_HID / 4; q++)
        out4[q] = make_float4(acc[4 * q], acc[4 * q + 1], acc[4 * q + 2], acc[4 * q + 3]);
}

// ---------------------------------------------------------------------------
// Layers 2/3 projection: d_A = elu(d_S + b) @ W   (W: [32,32])
// ---------------------------------------------------------------------------
__global__ void __launch_bounds__(256) proj_small_kernel(const float* __restrict__ W,
                                                         const float* __restrict__ b) {
    __shared__ float sW[D_HID * D_HID];
    __shared__ float sb[D_HID];
    for (int i = threadIdx.x; i < D_HID * D_HID; i += 256) sW[i] = W[i];
    if (threadIdx.x < D_HID) sb[threadIdx.x] = b[threadIdx.x];
    __syncthreads();

    int n = blockIdx.x * 256 + threadIdx.x;
    if (n >= N_NODES) return;

    float h[D_HID];
    const float4* src4 = reinterpret_cast<const float4*>(d_S) + (size_t)n * (D_HID / 4);
#pragma unroll
    for (int q = 0; q < D_HID / 4; q++) {
        float4 v = src4[q];
        h[4 * q + 0] = elu_f(v.x + sb[4 * q + 0]);
        h[4 * q + 1] = elu_f(v.y + sb[4 * q + 1]);
        h[4 * q + 2] = elu_f(v.z + sb[4 * q + 2]);
        h[4 * q + 3] = elu_f(v.w + sb[4 * q + 3]);
    }

    float4* out4 = reinterpret_cast<float4*>(d_A) + (size_t)n * (D_HID / 4);
#pragma unroll 4
    for (int j4 = 0; j4 < D_HID / 4; j4++) {
        float a0 = 0.f, a1 = 0.f, a2 = 0.f, a3 = 0.f;
#pragma unroll
        for (int k = 0; k < D_HID; k++) {
            const float* wr = &sW[k * D_HID + 4 * j4];
            float hk = h[k];
            a0 += hk * wr[0]; a1 += hk * wr[1]; a2 += hk * wr[2]; a3 += hk * wr[3];
        }
        out4[j4] = make_float4(a0, a1, a2, a3);
    }
}

// ---------------------------------------------------------------------------
// Zero the spmm accumulator
// ---------------------------------------------------------------------------
__global__ void __launch_bounds__(256) zeroS_kernel() {
    int i = blockIdx.x * 256 + threadIdx.x;
    if (i < N_NODES * (D_HID / 4))
        reinterpret_cast<float4*>(d_S)[i] = make_float4(0.f, 0.f, 0.f, 0.f);
}

// ---------------------------------------------------------------------------
// Edge scatter: d_S[row] += w * d_A[col], one thread per edge.
// Vectorized L2 atomics (red.global.add.v4.f32).
// ---------------------------------------------------------------------------
__global__ void __launch_bounds__(256) scatter_kernel(const int* __restrict__ row,
                                                      const int* __restrict__ col,
                                                      const float* __restrict__ ew,
                                                      int E) {
    int e = blockIdx.x * 256 + threadIdx.x;
    if (e >= E) return;
    int r = row[e];
    int c = col[e];
    float w = ew[e];

    const float4* src = reinterpret_cast<const float4*>(d_A) + (size_t)c * (D_HID / 4);
    float4* dst = reinterpret_cast<float4*>(d_S) + (size_t)r * (D_HID / 4);

#pragma unroll
    for (int q = 0; q < D_HID / 4; q++) {
        float4 v = __ldg(src + q);
        asm volatile("red.global.add.v4.f32 [%0], {%1, %2, %3, %4};"
                     :: "l"(dst + q), "f"(v.x * w), "f"(v.y * w), "f"(v.z * w), "f"(v.w * w)
                     : "memory");
    }
}

// ---------------------------------------------------------------------------
// Global sum pool with fused elu(.+b3). seg_ids sorted -> binary search the
// per-graph node range; block-local reduction, no atomics.
// ---------------------------------------------------------------------------
__device__ __forceinline__ int lower_bound_dev(const int* __restrict__ a, int n, int v) {
    int lo = 0, hi = n;
    while (lo < hi) {
        int mid = (lo + hi) >> 1;
        if (a[mid] < v) lo = mid + 1; else hi = mid;
    }
    return lo;
}

__global__ void __launch_bounds__(256) pool_kernel(const int* __restrict__ seg,
                                                   const float* __restrict__ b3) {
    int g = blockIdx.x;
    int lo = lower_bound_dev(seg, N_NODES, g);
    int hi = lower_bound_dev(seg, N_NODES, g + 1);

    int colid = threadIdx.x & 31;
    int sub = threadIdx.x >> 5;   // 8 sub-groups
    float bias = b3[colid];

    float acc = 0.f;
    for (int n = lo + sub; n < hi; n += 8) {
        float v = d_S[(size_t)n * D_HID + colid] + bias;
        acc += elu_f(v);
    }

    __shared__ float red[256];
    red[threadIdx.x] = acc;
    __syncthreads();
    if (threadIdx.x < 32) {
        float t = 0.f;
#pragma unroll
        for (int s = 0; s < 8; s++) t += red[s * 32 + threadIdx.x];
        d_pool[g * D_HID + threadIdx.x] = t;
    }
}

// ---------------------------------------------------------------------------
// Dense head: relu(g@Wd1+bd1) -> relu(@Wd2+bd2) -> sigmoid(@Wd3+bd3)
// One block (64 threads) per graph.
// ---------------------------------------------------------------------------
__global__ void __launch_bounds__(64) mlp_kernel(const float* __restrict__ Wd1,
                                                 const float* __restrict__ bd1,
                                                 const float* __restrict__ Wd2,
                                                 const float* __restrict__ bd2,
                                                 const float* __restrict__ Wd3,
                                                 const float* __restrict__ bd3,
                                                 float* __restrict__ out) {
    __shared__ float sW1[32 * 64];
    __shared__ float sW2[64 * 32];
    __shared__ float sW3[32];
    __shared__ float sg[32];
    __shared__ float sh1[64];
    __shared__ float sh2[32];

    int t = threadIdx.x;
    int r = blockIdx.x;
    for (int i = t; i < 32 * 64; i += 64) sW1[i] = Wd1[i];
    for (int i = t; i < 64 * 32; i += 64) sW2[i] = Wd2[i];
    if (t < 32) sW3[t] = Wd3[t];
    if (t < 32) sg[t] = d_pool[r * 32 + t];
    __syncthreads();

    // layer d1: 32 -> 64
    {
        float a = bd1[t];
#pragma unroll
        for (int k = 0; k < 32; k++) a += sg[k] * sW1[k * 64 + t];
        sh1[t] = fmaxf(a, 0.f);
    }
    __syncthreads();

    // layer d2: 64 -> 32
    if (t < 32) {
        float a = bd2[t];
#pragma unroll
        for (int k = 0; k < 64; k++) a += sh1[k] * sW2[k * 32 + t];
        sh2[t] = fmaxf(a, 0.f);
    }
    __syncthreads();

    // layer d3: 32 -> 1, sigmoid
    if (t == 0) {
        float a = bd3[0];
#pragma unroll
        for (int k = 0; k < 32; k++) a += sh2[k] * sW3[k];
        out[r] = 1.f / (1.f + expf(-a));
    }
}

// ---------------------------------------------------------------------------
// Launch
// ---------------------------------------------------------------------------
extern "C" void kernel_launch(void* const* d_in, const int* in_sizes, int n_in,
                              void* d_out, int out_size) {
    const float* x   = (const float*)d_in[0];
    const int*   ei  = (const int*)d_in[1];
    const float* ew  = (const float*)d_in[2];
    const int*   seg = (const int*)d_in[3];
    const float* W1  = (const float*)d_in[4];
    const float* b1  = (const float*)d_in[5];
    const float* W2  = (const float*)d_in[6];
    const float* b2  = (const float*)d_in[7];
    const float* W3  = (const float*)d_in[8];
    const float* b3  = (const float*)d_in[9];
    const float* Wd1 = (const float*)d_in[10];
    const float* bd1 = (const float*)d_in[11];
    const float* Wd2 = (const float*)d_in[12];
    const float* bd2 = (const float*)d_in[13];
    const float* Wd3 = (const float*)d_in[14];
    const float* bd3 = (const float*)d_in[15];
    float* out = (float*)d_out;

    int E = in_sizes[2];
    const int* row = ei;
    const int* col = ei + E;

    const int zgrid = (N_NODES * (D_HID / 4) + 255) / 256;
    const int sgrid = (E + 255) / 256;
    const int pgrid = (N_NODES + 255) / 256;

    // Layer 1
    proj1_kernel<<<(N_NODES + 127) / 128, 128>>>(x, W1);
    zeroS_kernel<<<zgrid, 256>>>();
    scatter_kernel<<<sgrid, 256>>>(row, col, ew, E);

    // Layer 2 (fused elu(S+b1) @ W2)
    proj_small_kernel<<<pgrid, 256>>>(W2, b1);
    zeroS_kernel<<<zgrid, 256>>>();
    scatter_kernel<<<sgrid, 256>>>(row, col, ew, E);

    // Layer 3 (fused elu(S+b2) @ W3)
    proj_small_kernel<<<pgrid, 256>>>(W3, b2);
    zeroS_kernel<<<zgrid, 256>>>();
    scatter_kernel<<<sgrid, 256>>>(row, col, ew, E);

    // Pool (fused elu(S+b3)) + dense head
    pool_kernel<<<N_GRAPHS, 256>>>(seg, b3);
    mlp_kernel<<<N_GRAPHS, 64>>>(Wd1, bd1, Wd2, bd2, Wd3, bd3, out);
}

// round 3
// speedup vs baseline: 2.0943x; 2.0943x over previous
#include <cuda_runtime.h>
#include <math.h>

#define N_NODES 100000
#define N_EDGES_MAX 3200000
#define N_GRAPHS 512
#define D_FEAT 128
#define D_HID 32
#define SCAN_B 512
#define NB_SCAN ((N_NODES + SCAN_B - 1) / SCAN_B)   // 196

// Scratch (allocation-free rule: __device__ globals; referenced ONLY in device code)
__device__ __align__(16) float d_A[N_NODES * D_HID];
__device__ __align__(16) float d_B[N_NODES * D_HID];
__device__ __align__(16) float d_S[N_NODES * D_HID];
__device__ float d_pool[N_GRAPHS * D_HID];
__device__ int d_deg[N_NODES];
__device__ int d_off[N_NODES + 1];
__device__ int d_cur[N_NODES];
__device__ int d_bsum[NB_SCAN];
__device__ __align__(8) float2 d_pk[N_EDGES_MAX];   // (col bits, w) grouped by row

__device__ __forceinline__ float elu_f(float x) { return x > 0.f ? x : expm1f(x); }

// ---------------------------------------------------------------------------
// Layer 1 projection: d_A = x @ W1   (x: [N,128], W1: [128,32])
// ---------------------------------------------------------------------------
__global__ void __launch_bounds__(128) proj1_kernel(const float* __restrict__ x,
                                                    const float* __restrict__ W) {
    __shared__ float sW[D_FEAT * D_HID];
    for (int i = threadIdx.x; i < D_FEAT * D_HID; i += 128) sW[i] = W[i];
    __syncthreads();

    int n = blockIdx.x * 128 + threadIdx.x;
    if (n >= N_NODES) return;

    float acc[D_HID];
#pragma unroll
    for (int j = 0; j < D_HID; j++) acc[j] = 0.f;

    const float4* xr = reinterpret_cast<const float4*>(x) + (size_t)n * (D_FEAT / 4);
#pragma unroll 4
    for (int k4 = 0; k4 < D_FEAT / 4; k4++) {
        float4 v = xr[k4];
        const float* w0 = &sW[(k4 * 4 + 0) * D_HID];
        const float* w1 = &sW[(k4 * 4 + 1) * D_HID];
        const float* w2 = &sW[(k4 * 4 + 2) * D_HID];
        const float* w3 = &sW[(k4 * 4 + 3) * D_HID];
#pragma unroll
        for (int j = 0; j < D_HID; j++)
            acc[j] += v.x * w0[j] + v.y * w1[j] + v.z * w2[j] + v.w * w3[j];
    }

    float4* out4 = reinterpret_cast<float4*>(d_A) + (size_t)n * (D_HID / 4);
#pragma unroll
    for (int q = 0; q < D_HID / 4; q++)
        out4[q] = make_float4(acc[4 * q], acc[4 * q + 1], acc[4 * q + 2], acc[4 * q + 3]);
}

// ---------------------------------------------------------------------------
// CSR build
// ---------------------------------------------------------------------------
__global__ void __launch_bounds__(256) zero_deg_kernel() {
    int i = blockIdx.x * 256 + threadIdx.x;
    if (i < N_NODES) d_deg[i] = 0;
}

__global__ void __launch_bounds__(256) count_kernel(const int* __restrict__ row, int E) {
    int e = blockIdx.x * 256 + threadIdx.x;
    if (e < E) atomicAdd(&d_deg[row[e]], 1);
}

__global__ void __launch_bounds__(SCAN_B) scan1_kernel() {
    __shared__ int sh[SCAN_B];
    int i = blockIdx.x * SCAN_B + threadIdx.x;
    int v = (i < N_NODES) ? d_deg[i] : 0;
    sh[threadIdx.x] = v;
    __syncthreads();
    for (int s = 1; s < SCAN_B; s <<= 1) {
        int t = (threadIdx.x >= s) ? sh[threadIdx.x - s] : 0;
        __syncthreads();
        sh[threadIdx.x] += t;
        __syncthreads();
    }
    if (i < N_NODES) d_off[i] = sh[threadIdx.x] - v;   // exclusive
    if (threadIdx.x == SCAN_B - 1) d_bsum[blockIdx.x] = sh[SCAN_B - 1];
}

__global__ void __launch_bounds__(256) scan2_kernel() {
    __shared__ int sh[256];
    int v = (threadIdx.x < NB_SCAN) ? d_bsum[threadIdx.x] : 0;
    sh[threadIdx.x] = v;
    __syncthreads();
    for (int s = 1; s < 256; s <<= 1) {
        int t = (threadIdx.x >= s) ? sh[threadIdx.x - s] : 0;
        __syncthreads();
        sh[threadIdx.x] += t;
        __syncthreads();
    }
    if (threadIdx.x < NB_SCAN) d_bsum[threadIdx.x] = sh[threadIdx.x] - v;  // exclusive
}

__global__ void __launch_bounds__(SCAN_B) scan3_kernel(int E) {
    int i = blockIdx.x * SCAN_B + threadIdx.x;
    if (i < N_NODES) {
        int o = d_off[i] + d_bsum[blockIdx.x];
        d_off[i] = o;
        d_cur[i] = o;
    }
    if (i == 0) d_off[N_NODES] = E;
}

__global__ void __launch_bounds__(256) fill_kernel(const int* __restrict__ row,
                                                   const int* __restrict__ col,
                                                   const float* __restrict__ ew, int E) {
    int e = blockIdx.x * 256 + threadIdx.x;
    if (e >= E) return;
    int r = row[e];
    int pos = atomicAdd(&d_cur[r], 1);
    d_pk[pos] = make_float2(__int_as_float(col[e]), ew[e]);
}

// ---------------------------------------------------------------------------
// Fused SpMM gather + elu(+bias) [+ 32x32 projection].
// One warp per node. PASS selects src/dst (device-code symbol refs only):
//   PASS 0: src=d_A, dst=d_B, PROJ
//   PASS 1: src=d_B, dst=d_A, PROJ
//   PASS 2: src=d_A, dst=d_S, no PROJ
// ---------------------------------------------------------------------------
template <int PASS, bool PROJ>
__global__ void __launch_bounds__(256) spmm_gather_kernel(const float* __restrict__ W,
                                                          const float* __restrict__ b) {
    const float* __restrict__ src = (PASS == 1) ? d_B : d_A;
    float* __restrict__ dst = (PASS == 0) ? d_B : (PASS == 1) ? d_A : d_S;

    __shared__ float sW[D_HID * D_HID];
    __shared__ float sb[D_HID];
    if (PROJ)
        for (int i = threadIdx.x; i < D_HID * D_HID; i += 256) sW[i] = W[i];
    if (threadIdx.x < D_HID) sb[threadIdx.x] = b[threadIdx.x];
    __syncthreads();

    int wid = blockIdx.x * 8 + (threadIdx.x >> 5);
    if (wid >= N_NODES) return;
    int lane = threadIdx.x & 31;

    int beg = d_off[wid];
    int end = d_off[wid + 1];

    float acc = 0.f;
    int e = beg;
    for (; e + 4 <= end; e += 4) {
        float2 p0 = d_pk[e + 0];
        float2 p1 = d_pk[e + 1];
        float2 p2 = d_pk[e + 2];
        float2 p3 = d_pk[e + 3];
        float v0 = __ldg(src + (size_t)__float_as_int(p0.x) * D_HID + lane);
        float v1 = __ldg(src + (size_t)__float_as_int(p1.x) * D_HID + lane);
        float v2 = __ldg(src + (size_t)__float_as_int(p2.x) * D_HID + lane);
        float v3 = __ldg(src + (size_t)__float_as_int(p3.x) * D_HID + lane);
        acc += p0.y * v0;
        acc += p1.y * v1;
        acc += p2.y * v2;
        acc += p3.y * v3;
    }
    for (; e < end; e++) {
        float2 p = d_pk[e];
        acc += p.y * __ldg(src + (size_t)__float_as_int(p.x) * D_HID + lane);
    }

    float h = elu_f(acc + sb[lane]);

    if (PROJ) {
        float o = 0.f;
#pragma unroll
        for (int k = 0; k < D_HID; k++)
            o += __shfl_sync(0xffffffffu, h, k) * sW[k * D_HID + lane];
        dst[(size_t)wid * D_HID + lane] = o;
    } else {
        dst[(size_t)wid * D_HID + lane] = h;
    }
}

// ---------------------------------------------------------------------------
// Global sum pool. seg_ids sorted -> binary search per graph, no atomics.
// ---------------------------------------------------------------------------
__device__ __forceinline__ int lower_bound_dev(const int* __restrict__ a, int n, int v) {
    int lo = 0, hi = n;
    while (lo < hi) {
        int mid = (lo + hi) >> 1;
        if (a[mid] < v) lo = mid + 1; else hi = mid;
    }
    return lo;
}

__global__ void __launch_bounds__(256) pool_kernel(const int* __restrict__ seg) {
    int g = blockIdx.x;
    int lo = lower_bound_dev(seg, N_NODES, g);
    int hi = lower_bound_dev(seg, N_NODES, g + 1);

    int colid = threadIdx.x & 31;
    int sub = threadIdx.x >> 5;

    float acc = 0.f;
    for (int n = lo + sub; n < hi; n += 8)
        acc += d_S[(size_t)n * D_HID + colid];

    __shared__ float red[256];
    red[threadIdx.x] = acc;
    __syncthreads();
    if (threadIdx.x < 32) {
        float t = 0.f;
#pragma unroll
        for (int s = 0; s < 8; s++) t += red[s * 32 + threadIdx.x];
        d_pool[g * D_HID + threadIdx.x] = t;
    }
}

// ---------------------------------------------------------------------------
// Dense head
// ---------------------------------------------------------------------------
__global__ void __launch_bounds__(64) mlp_kernel(const float* __restrict__ Wd1,
                                                 const float* __restrict__ bd1,
                                                 const float* __restrict__ Wd2,
                                                 const float* __restrict__ bd2,
                                                 const float* __restrict__ Wd3,
                                                 const float* __restrict__ bd3,
                                                 float* __restrict__ out) {
    __shared__ float sW1[32 * 64];
    __shared__ float sW2[64 * 32];
    __shared__ float sW3[32];
    __shared__ float sg[32];
    __shared__ float sh1[64];
    __shared__ float sh2[32];

    int t = threadIdx.x;
    int r = blockIdx.x;
    for (int i = t; i < 32 * 64; i += 64) sW1[i] = Wd1[i];
    for (int i = t; i < 64 * 32; i += 64) sW2[i] = Wd2[i];
    if (t < 32) sW3[t] = Wd3[t];
    if (t < 32) sg[t] = d_pool[r * 32 + t];
    __syncthreads();

    {
        float a = bd1[t];
#pragma unroll
        for (int k = 0; k < 32; k++) a += sg[k] * sW1[k * 64 + t];
        sh1[t] = fmaxf(a, 0.f);
    }
    __syncthreads();

    if (t < 32) {
        float a = bd2[t];
#pragma unroll
        for (int k = 0; k < 64; k++) a += sh1[k] * sW2[k * 32 + t];
        sh2[t] = fmaxf(a, 0.f);
    }
    __syncthreads();

    if (t == 0) {
        float a = bd3[0];
#pragma unroll
        for (int k = 0; k < 32; k++) a += sh2[k] * sW3[k];
        out[r] = 1.f / (1.f + expf(-a));
    }
}

// ---------------------------------------------------------------------------
// Launch
// ---------------------------------------------------------------------------
extern "C" void kernel_launch(void* const* d_in, const int* in_sizes, int n_in,
                              void* d_out, int out_size) {
    const float* x   = (const float*)d_in[0];
    const int*   ei  = (const int*)d_in[1];
    const float* ew  = (const float*)d_in[2];
    const int*   seg = (const int*)d_in[3];
    const float* W1  = (const float*)d_in[4];
    const float* b1  = (const float*)d_in[5];
    const float* W2  = (const float*)d_in[6];
    const float* b2  = (const float*)d_in[7];
    const float* W3  = (const float*)d_in[8];
    const float* b3  = (const float*)d_in[9];
    const float* Wd1 = (const float*)d_in[10];
    const float* bd1 = (const float*)d_in[11];
    const float* Wd2 = (const float*)d_in[12];
    const float* bd2 = (const float*)d_in[13];
    const float* Wd3 = (const float*)d_in[14];
    const float* bd3 = (const float*)d_in[15];
    float* out = (float*)d_out;

    int E = in_sizes[2];
    const int* row = ei;
    const int* col = ei + E;

    const int egrid = (E + 255) / 256;
    const int ggrid = (N_NODES + 7) / 8;        // warp-per-node, 8 warps/block

    // CSR build
    zero_deg_kernel<<<(N_NODES + 255) / 256, 256>>>();
    count_kernel<<<egrid, 256>>>(row, E);
    scan1_kernel<<<NB_SCAN, SCAN_B>>>();
    scan2_kernel<<<1, 256>>>();
    scan3_kernel<<<NB_SCAN, SCAN_B>>>(E);
    fill_kernel<<<egrid, 256>>>(row, col, ew, E);

    // Layer 1 projection
    proj1_kernel<<<(N_NODES + 127) / 128, 128>>>(x, W1);

    // Fused SpMM + elu + projection chain (src/dst chosen inside by PASS)
    spmm_gather_kernel<0, true><<<ggrid, 256>>>(W2, b1);    // A -> B
    spmm_gather_kernel<1, true><<<ggrid, 256>>>(W3, b2);    // B -> A
    spmm_gather_kernel<2, false><<<ggrid, 256>>>(nullptr, b3); // A -> S

    // Pool + dense head
    pool_kernel<<<N_GRAPHS, 256>>>(seg);
    mlp_kernel<<<N_GRAPHS, 64>>>(Wd1, bd1, Wd2, bd2, Wd3, bd3, out);
}